// round 3
// baseline (speedup 1.0000x reference)
#include <cuda_runtime.h>
#include <cstdint>

// Suffix (reverse cumulative) max along last dim.
// (8, 1, 2048, 2048) fp32 -> 16384 rows x 2048 cols.
// TWO rows per CTA, 256 threads, 8 elems/thread/row via float4.
// Two independent dependency chains per thread, one barrier.

#define ROW_LEN 2048
#define THREADS 256

__device__ __forceinline__ float neg_inf() {
    return __int_as_float(0xff800000);
}

__global__ void __launch_bounds__(THREADS)
suffix_max_kernel(const float* __restrict__ in, float* __restrict__ out) {
    const size_t base = (size_t)blockIdx.x * (2 * ROW_LEN);
    const float4* __restrict__ rin0  = reinterpret_cast<const float4*>(in  + base);
    const float4* __restrict__ rin1  = reinterpret_cast<const float4*>(in  + base + ROW_LEN);
    float4* __restrict__       rout0 = reinterpret_cast<float4*>(out + base);
    float4* __restrict__       rout1 = reinterpret_cast<float4*>(out + base + ROW_LEN);

    const int t    = threadIdx.x;
    const int lane = t & 31;
    const int warp = t >> 5;
    const int vi   = t * 2;

    // ---- loads: 4 independent LDG.128 (2 per row) ----
    float4 a0 = rin0[vi + 0];
    float4 b0 = rin0[vi + 1];
    float4 a1 = rin1[vi + 0];
    float4 b1 = rin1[vi + 1];

    // ---- per-thread suffix max (two independent chains, ILP) ----
    b0.z = fmaxf(b0.z, b0.w);  b1.z = fmaxf(b1.z, b1.w);
    b0.y = fmaxf(b0.y, b0.z);  b1.y = fmaxf(b1.y, b1.z);
    b0.x = fmaxf(b0.x, b0.y);  b1.x = fmaxf(b1.x, b1.y);
    a0.w = fmaxf(a0.w, b0.x);  a1.w = fmaxf(a1.w, b1.x);
    a0.z = fmaxf(a0.z, a0.w);  a1.z = fmaxf(a1.z, a1.w);
    a0.y = fmaxf(a0.y, a0.z);  a1.y = fmaxf(a1.y, a1.z);
    a0.x = fmaxf(a0.x, a0.y);  a1.x = fmaxf(a1.x, a1.y);

    // ---- warp-level inclusive suffix scan of chunk maxima (both rows) ----
    float incl0 = a0.x, incl1 = a1.x;
    #pragma unroll
    for (int off = 1; off < 32; off <<= 1) {
        float x0 = __shfl_down_sync(0xffffffffu, incl0, off);
        float x1 = __shfl_down_sync(0xffffffffu, incl1, off);
        if (lane + off < 32) { incl0 = fmaxf(incl0, x0); incl1 = fmaxf(incl1, x1); }
    }
    float ex0 = __shfl_down_sync(0xffffffffu, incl0, 1);
    float ex1 = __shfl_down_sync(0xffffffffu, incl1, 1);
    if (lane == 31) { ex0 = neg_inf(); ex1 = neg_inf(); }

    // ---- cross-warp carry via smem, single barrier ----
    __shared__ float wm0[8], wm1[8];
    if (lane == 0) { wm0[warp] = incl0; wm1[warp] = incl1; }
    __syncthreads();

    float c0 = ex0, c1 = ex1;
    #pragma unroll
    for (int j = 1; j < 8; ++j) {
        int w = warp + j;
        if (w < 8) { c0 = fmaxf(c0, wm0[w]); c1 = fmaxf(c1, wm1[w]); }
    }

    // ---- apply carries and store ----
    a0.x = fmaxf(a0.x, c0); a0.y = fmaxf(a0.y, c0);
    a0.z = fmaxf(a0.z, c0); a0.w = fmaxf(a0.w, c0);
    b0.x = fmaxf(b0.x, c0); b0.y = fmaxf(b0.y, c0);
    b0.z = fmaxf(b0.z, c0); b0.w = fmaxf(b0.w, c0);

    a1.x = fmaxf(a1.x, c1); a1.y = fmaxf(a1.y, c1);
    a1.z = fmaxf(a1.z, c1); a1.w = fmaxf(a1.w, c1);
    b1.x = fmaxf(b1.x, c1); b1.y = fmaxf(b1.y, c1);
    b1.z = fmaxf(b1.z, c1); b1.w = fmaxf(b1.w, c1);

    rout0[vi + 0] = a0;
    rout0[vi + 1] = b0;
    rout1[vi + 0] = a1;
    rout1[vi + 1] = b1;
}

extern "C" void kernel_launch(void* const* d_in, const int* in_sizes, int n_in,
                              void* d_out, int out_size) {
    const float* x = (const float*)d_in[0];
    float* out = (float*)d_out;
    const int n_blocks = out_size / (2 * ROW_LEN);   // 8192
    suffix_max_kernel<<<n_blocks, THREADS>>>(x, out);
}

// round 4
// speedup vs baseline: 1.3589x; 1.3589x over previous
#include <cuda_runtime.h>
#include <cstdint>

// Suffix (reverse cumulative) max along last dim.
// (8, 1, 2048, 2048) fp32 -> 16384 rows x 2048 cols.
// One CTA per row, 256 threads. Thread t owns float4 #t (lo) and #(256+t) (hi)
// -> every LDG.128/STG.128 is perfectly coalesced (4 lines/warp, min wavefronts).

#define ROW_LEN 2048
#define THREADS 256
#define NV4     512          // float4 per row

__device__ __forceinline__ float neg_inf() {
    return __int_as_float(0xff800000);
}

__global__ void __launch_bounds__(THREADS)
suffix_max_kernel(const float* __restrict__ in, float* __restrict__ out) {
    const size_t row_off = (size_t)blockIdx.x * ROW_LEN;
    const float4* __restrict__ rin  = reinterpret_cast<const float4*>(in  + row_off);
    float4* __restrict__       rout = reinterpret_cast<float4*>(out + row_off);

    const int t    = threadIdx.x;
    const int lane = t & 31;
    const int warp = t >> 5;

    // ---- coalesced loads: lo chunk = float4[t], hi chunk = float4[256+t] ----
    float4 lo = rin[t];
    float4 hi = rin[THREADS + t];

    // ---- suffix max within each float4 (independent chains) ----
    lo.z = fmaxf(lo.z, lo.w);   hi.z = fmaxf(hi.z, hi.w);
    lo.y = fmaxf(lo.y, lo.z);   hi.y = fmaxf(hi.y, hi.z);
    lo.x = fmaxf(lo.x, lo.y);   hi.x = fmaxf(hi.x, hi.y);

    // ---- warp-level inclusive suffix scans of chunk maxima (lo & hi) ----
    float ilo = lo.x, ihi = hi.x;
    #pragma unroll
    for (int off = 1; off < 32; off <<= 1) {
        float xl = __shfl_down_sync(0xffffffffu, ilo, off);
        float xh = __shfl_down_sync(0xffffffffu, ihi, off);
        if (lane + off < 32) { ilo = fmaxf(ilo, xl); ihi = fmaxf(ihi, xh); }
    }
    // exclusive (carry from lanes strictly right, within warp)
    float exlo = __shfl_down_sync(0xffffffffu, ilo, 1);
    float exhi = __shfl_down_sync(0xffffffffu, ihi, 1);
    if (lane == 31) { exlo = neg_inf(); exhi = neg_inf(); }

    // ---- cross-warp maxima via smem, single barrier ----
    __shared__ float wlo[8], whi[8];
    if (lane == 0) { wlo[warp] = ilo; whi[warp] = ihi; }
    __syncthreads();

    // hi-chunk carry: warps strictly right in the hi half
    float chi = exhi;
    #pragma unroll
    for (int j = 1; j < 8; ++j)
        if (warp + j < 8) chi = fmaxf(chi, whi[warp + j]);

    // max over the whole hi half (applies to every lo chunk)
    float hall = whi[0];
    #pragma unroll
    for (int j = 1; j < 8; ++j) hall = fmaxf(hall, whi[j]);

    // lo-chunk carry: warps strictly right in lo half, plus all of hi half
    float clo = fmaxf(exlo, hall);
    #pragma unroll
    for (int j = 1; j < 8; ++j)
        if (warp + j < 8) clo = fmaxf(clo, wlo[warp + j]);

    // ---- apply carries and store (coalesced) ----
    lo.x = fmaxf(lo.x, clo); lo.y = fmaxf(lo.y, clo);
    lo.z = fmaxf(lo.z, clo); lo.w = fmaxf(lo.w, clo);
    hi.x = fmaxf(hi.x, chi); hi.y = fmaxf(hi.y, chi);
    hi.z = fmaxf(hi.z, chi); hi.w = fmaxf(hi.w, chi);

    rout[t]           = lo;
    rout[THREADS + t] = hi;
}

extern "C" void kernel_launch(void* const* d_in, const int* in_sizes, int n_in,
                              void* d_out, int out_size) {
    const float* x = (const float*)d_in[0];
    float* out = (float*)d_out;
    const int n_rows = out_size / ROW_LEN;   // 16384
    suffix_max_kernel<<<n_rows, THREADS>>>(x, out);
}

// round 5
// speedup vs baseline: 1.3669x; 1.0059x over previous
#include <cuda_runtime.h>
#include <cstdint>

// Suffix (reverse cumulative) max along last dim.
// (8, 1, 2048, 2048) fp32 -> 16384 rows x 2048 cols.
// One CTA per row, 256 threads, block-split coalesced chunks (R4 shape),
// with all predication stripped from the scan (R5: ALU diet).

#define ROW_LEN 2048
#define THREADS 256

#define NEG_INF __int_as_float(0xff800000)

__global__ void __launch_bounds__(THREADS)
suffix_max_kernel(const float* __restrict__ in, float* __restrict__ out) {
    const unsigned row_off = blockIdx.x * (unsigned)ROW_LEN;   // <= 2^25 elems, 32-bit safe
    const float4* __restrict__ rin  = reinterpret_cast<const float4*>(in  + row_off);
    float4* __restrict__       rout = reinterpret_cast<float4*>(out + row_off);

    const int t    = threadIdx.x;
    const int lane = t & 31;
    const int warp = t >> 5;

    // padded cross-warp maxima: [0..7] real, [8..15] = -inf (no guards needed)
    __shared__ float wlo[16], whi[16];
    if (t < 8) { wlo[8 + t] = NEG_INF; whi[8 + t] = NEG_INF; }

    // ---- coalesced loads: lo chunk = float4[t], hi chunk = float4[256+t] ----
    float4 lo = rin[t];
    float4 hi = rin[THREADS + t];

    // ---- suffix max within each float4 (two independent chains) ----
    lo.z = fmaxf(lo.z, lo.w);   hi.z = fmaxf(hi.z, hi.w);
    lo.y = fmaxf(lo.y, lo.z);   hi.y = fmaxf(hi.y, hi.z);
    lo.x = fmaxf(lo.x, lo.y);   hi.x = fmaxf(hi.x, hi.y);

    // ---- warp-level inclusive suffix scans (unpredicated: oob shfl returns self) ----
    float ilo = lo.x, ihi = hi.x;
    #pragma unroll
    for (int off = 1; off < 32; off <<= 1) {
        ilo = fmaxf(ilo, __shfl_down_sync(0xffffffffu, ilo, off));
        ihi = fmaxf(ihi, __shfl_down_sync(0xffffffffu, ihi, off));
    }
    // exclusive carries (lanes strictly to the right within warp)
    float exlo = __shfl_down_sync(0xffffffffu, ilo, 1);
    float exhi = __shfl_down_sync(0xffffffffu, ihi, 1);
    if (lane == 31) { exlo = NEG_INF; exhi = NEG_INF; }

    if (lane == 0) { wlo[warp] = ilo; whi[warp] = ihi; }
    __syncthreads();

    // hi-chunk carry: warps strictly right in hi half (padded -> no bounds checks)
    float chi = exhi;
    #pragma unroll
    for (int j = 1; j < 8; ++j) chi = fmaxf(chi, whi[warp + j]);

    // max over the entire hi half (tree)
    float h01 = fmaxf(whi[0], whi[1]);
    float h23 = fmaxf(whi[2], whi[3]);
    float h45 = fmaxf(whi[4], whi[5]);
    float h67 = fmaxf(whi[6], whi[7]);
    float hall = fmaxf(fmaxf(h01, h23), fmaxf(h45, h67));

    // lo-chunk carry: warps strictly right in lo half + all of hi half
    float clo = fmaxf(exlo, hall);
    #pragma unroll
    for (int j = 1; j < 8; ++j) clo = fmaxf(clo, wlo[warp + j]);

    // ---- apply carries and store (coalesced) ----
    lo.x = fmaxf(lo.x, clo); lo.y = fmaxf(lo.y, clo);
    lo.z = fmaxf(lo.z, clo); lo.w = fmaxf(lo.w, clo);
    hi.x = fmaxf(hi.x, chi); hi.y = fmaxf(hi.y, chi);
    hi.z = fmaxf(hi.z, chi); hi.w = fmaxf(hi.w, chi);

    rout[t]           = lo;
    rout[THREADS + t] = hi;
}

extern "C" void kernel_launch(void* const* d_in, const int* in_sizes, int n_in,
                              void* d_out, int out_size) {
    const float* x = (const float*)d_in[0];
    float* out = (float*)d_out;
    const int n_rows = out_size / ROW_LEN;   // 16384
    suffix_max_kernel<<<n_rows, THREADS>>>(x, out);
}

// round 6
// speedup vs baseline: 1.3679x; 1.0007x over previous
#include <cuda_runtime.h>
#include <cstdint>

// Suffix (reverse cumulative) max along last dim.
// (8, 1, 2048, 2048) fp32 -> 16384 rows x 2048 cols.
// 2 rows per CTA, 256 threads. Thread t owns floats [8t..8t+7] of each row
// via 256-bit ld/st.global.v8.f32 (sm_100+). One barrier per CTA.

#define ROW_LEN 2048
#define THREADS 256
#define NEG_INF __int_as_float(0xff800000)

#define LDG256(p, v) \
    asm volatile("ld.global.v8.f32 {%0,%1,%2,%3,%4,%5,%6,%7}, [%8];" \
        : "=f"(v[0]), "=f"(v[1]), "=f"(v[2]), "=f"(v[3]),            \
          "=f"(v[4]), "=f"(v[5]), "=f"(v[6]), "=f"(v[7])             \
        : "l"(p))

#define STG256(p, v) \
    asm volatile("st.global.v8.f32 [%0], {%1,%2,%3,%4,%5,%6,%7,%8};" \
        :: "l"(p),                                                    \
           "f"(v[0]), "f"(v[1]), "f"(v[2]), "f"(v[3]),               \
           "f"(v[4]), "f"(v[5]), "f"(v[6]), "f"(v[7])                \
        : "memory")

__global__ void __launch_bounds__(THREADS)
suffix_max_kernel(const float* __restrict__ in, float* __restrict__ out) {
    const unsigned base = blockIdx.x * (2u * ROW_LEN);
    const unsigned off  = base + threadIdx.x * 8u;

    const float* __restrict__ p0 = in + off;            // row 0 chunk
    const float* __restrict__ p1 = p0 + ROW_LEN;        // row 1 chunk
    float* __restrict__ q0 = out + off;
    float* __restrict__ q1 = q0 + ROW_LEN;

    const int t    = threadIdx.x;
    const int lane = t & 31;
    const int warp = t >> 5;

    // padded cross-warp maxima: [0..7] real, [8..15] = -inf
    __shared__ float w0[16], w1[16];
    if (t < 8) { w0[8 + t] = NEG_INF; w1[8 + t] = NEG_INF; }

    // ---- 256-bit loads, two independent streams ----
    float a[8], b[8];
    LDG256(p0, a);
    LDG256(p1, b);

    // ---- suffix max within each 8-chunk (two independent chains, ILP) ----
    a[6] = fmaxf(a[6], a[7]);   b[6] = fmaxf(b[6], b[7]);
    a[5] = fmaxf(a[5], a[6]);   b[5] = fmaxf(b[5], b[6]);
    a[4] = fmaxf(a[4], a[5]);   b[4] = fmaxf(b[4], b[5]);
    a[3] = fmaxf(a[3], a[4]);   b[3] = fmaxf(b[3], b[4]);
    a[2] = fmaxf(a[2], a[3]);   b[2] = fmaxf(b[2], b[3]);
    a[1] = fmaxf(a[1], a[2]);   b[1] = fmaxf(b[1], b[2]);
    a[0] = fmaxf(a[0], a[1]);   b[0] = fmaxf(b[0], b[1]);

    // ---- warp-level inclusive suffix scans (unpredicated, oob shfl = self) ----
    float i0 = a[0], i1 = b[0];
    #pragma unroll
    for (int off2 = 1; off2 < 32; off2 <<= 1) {
        i0 = fmaxf(i0, __shfl_down_sync(0xffffffffu, i0, off2));
        i1 = fmaxf(i1, __shfl_down_sync(0xffffffffu, i1, off2));
    }
    // exclusive carries (lanes strictly to the right within warp)
    float e0 = __shfl_down_sync(0xffffffffu, i0, 1);
    float e1 = __shfl_down_sync(0xffffffffu, i1, 1);
    if (lane == 31) { e0 = NEG_INF; e1 = NEG_INF; }

    if (lane == 0) { w0[warp] = i0; w1[warp] = i1; }
    __syncthreads();

    // cross-warp carries (padded -> straight-line, broadcast LDS)
    float c0 = e0, c1 = e1;
    #pragma unroll
    for (int j = 1; j < 8; ++j) {
        c0 = fmaxf(c0, w0[warp + j]);
        c1 = fmaxf(c1, w1[warp + j]);
    }

    // ---- apply carries and store ----
    #pragma unroll
    for (int k = 0; k < 8; ++k) {
        a[k] = fmaxf(a[k], c0);
        b[k] = fmaxf(b[k], c1);
    }

    STG256(q0, a);
    STG256(q1, b);
}

extern "C" void kernel_launch(void* const* d_in, const int* in_sizes, int n_in,
                              void* d_out, int out_size) {
    const float* x = (const float*)d_in[0];
    float* out = (float*)d_out;
    const int n_blocks = out_size / (2 * ROW_LEN);   // 8192
    suffix_max_kernel<<<n_blocks, THREADS>>>(x, out);
}